// round 2
// baseline (speedup 1.0000x reference)
#include <cuda_runtime.h>
#include <cstdint>

// Problem constants (fixed-shape problem)
#define NQ   50000   // queries
#define NMS  50000   // support points
#define NH   32      // neighbors per query
#define NK   15      // kernel points
#define NC   64      // input channels
#define ND   64      // output channels
#define KCDIM 960    // NK*NC flattened contraction dim
#define KPAD 50048   // NQ padded to multiple of 128 (391*128)

// Scratch: weighted[n][k][c] (already scaled by 1/neighbor_num), padded rows stay 0.
__device__ float g_wt[(size_t)KPAD * KCDIM];

// ---------------- f32x2 packed-FMA helpers (Blackwell FFMA2 path) ----------------
__device__ __forceinline__ unsigned long long ffma2(unsigned long long a,
                                                    unsigned long long b,
                                                    unsigned long long c) {
    unsigned long long d;
    asm("fma.rn.f32x2 %0, %1, %2, %3;" : "=l"(d) : "l"(a), "l"(b), "l"(c));
    return d;
}
__device__ __forceinline__ unsigned long long splat2(float v) {
    unsigned long long d;
    asm("mov.b64 %0, {%1, %1};" : "=l"(d) : "f"(v));
    return d;
}
__device__ __forceinline__ float2 unpack2(unsigned long long v) {
    float2 r;
    asm("mov.b64 {%0, %1}, %2;" : "=f"(r.x), "=f"(r.y) : "l"(v));
    return r;
}

// =============================================================================
// Kernel 1: per-query influence weights + neighbor aggregation
//   weighted[n,k,c] = (1/nnum) * sum_h w[n,h,k] * x[idx[n,h], c]
// One warp per query; 8 queries per 256-thread block.
// Stage 1: lane = neighbor h  -> w[h][k] into smem
// Stage 2: lane = channel c (owns c and c+32), k packed in f32x2 pairs
// =============================================================================
__global__ void __launch_bounds__(256) kpconv_stage1(
    const float* __restrict__ q_pts, const float* __restrict__ s_pts,
    const int*   __restrict__ nbi,   const float* __restrict__ x,
    const float* __restrict__ kp)
{
    __shared__ float ws[8][NH][16];   // 15 kernel pts + 1 zero pad
    __shared__ int   idxs[8][NH];
    const int warp = threadIdx.x >> 5;
    const int lane = threadIdx.x & 31;
    const int n    = blockIdx.x * 8 + warp;   // grid sized exactly NQ/8

    // ---- stage 1: lane = h ----
    const int idx = __ldg(&nbi[n * NH + lane]);
    const float qx = q_pts[n*3+0], qy = q_pts[n*3+1], qz = q_pts[n*3+2];
    const float dx = __ldg(&s_pts[idx*3+0]) - qx;
    const float dy = __ldg(&s_pts[idx*3+1]) - qy;
    const float dz = __ldg(&s_pts[idx*3+2]) - qz;
    #pragma unroll
    for (int k = 0; k < NK; k++) {
        const float ex = dx - kp[k*3+0];
        const float ey = dy - kp[k*3+1];
        const float ez = dz - kp[k*3+2];
        const float d2 = ex*ex + ey*ey + ez*ez;
        // sqrt(d2) = d2 * rsqrt(d2); guard d2=0
        const float r  = __frsqrt_rn(fmaxf(d2, 1e-24f));
        const float w  = 1.0f - (d2 * r) * (1.0f / 1.2f);
        ws[warp][lane][k] = fmaxf(w, 0.0f);
    }
    ws[warp][lane][15] = 0.0f;
    idxs[warp][lane] = idx;
    __syncwarp();

    // ---- stage 2: lane = channel ----
    unsigned long long a0[8], a1[8];   // k-pairs (2j,2j+1) for channels lane / lane+32
    #pragma unroll
    for (int j = 0; j < 8; j++) { a0[j] = 0ull; a1[j] = 0ull; }
    int cnt = 0;

    #pragma unroll 4
    for (int h = 0; h < NH; h++) {
        const int ih = idxs[warp][h];
        const float* xr = x + (size_t)ih * NC;
        const float x0 = __ldg(&xr[lane]);
        const float x1 = __ldg(&xr[lane + 32]);
        // validity: sum over all 64 channels > 0  (warp allreduce)
        float rs = x0 + x1;
        #pragma unroll
        for (int o = 16; o > 0; o >>= 1) rs += __shfl_xor_sync(0xffffffffu, rs, o);
        cnt += (rs > 0.0f) ? 1 : 0;

        const unsigned long long xx0 = splat2(x0);
        const unsigned long long xx1 = splat2(x1);
        const ulonglong2* wp = (const ulonglong2*)&ws[warp][h][0];
        #pragma unroll
        for (int j = 0; j < 4; j++) {
            const ulonglong2 w2 = wp[j];   // (w[4j],w[4j+1]) , (w[4j+2],w[4j+3])
            a0[2*j+0] = ffma2(w2.x, xx0, a0[2*j+0]);
            a0[2*j+1] = ffma2(w2.y, xx0, a0[2*j+1]);
            a1[2*j+0] = ffma2(w2.x, xx1, a1[2*j+0]);
            a1[2*j+1] = ffma2(w2.y, xx1, a1[2*j+1]);
        }
    }

    const float inv = 1.0f / (float)(cnt > 0 ? cnt : 1);
    float* outw = g_wt + (size_t)n * KCDIM;
    #pragma unroll
    for (int j = 0; j < 8; j++) {
        const float2 v0 = unpack2(a0[j]);
        const float2 v1 = unpack2(a1[j]);
        const int k = 2 * j;
        outw[k*64 + lane]      = v0.x * inv;
        outw[k*64 + 32 + lane] = v1.x * inv;
        if (k + 1 < NK) {
            outw[(k+1)*64 + lane]      = v0.y * inv;
            outw[(k+1)*64 + 32 + lane] = v1.y * inv;
        }
    }
}

// =============================================================================
// Kernel 2: out[N,64] = g_wt[N,960] @ W[960,64]   (fp32, f32x2 packed FMA)
// BM=128 rows/block, full 64 cols, BK=32. 256 threads, thread tile 8x4
// (4 row-pairs x 4 cols => 16 FFMA2 per k-step).
// =============================================================================
#define BM  128
#define BK  32
#define STR 132   // transposed-S row stride (x4 bytes, keeps LDS.128 aligned)

__global__ void __launch_bounds__(256) kpconv_stage2(
    const float* __restrict__ W, float* __restrict__ out)
{
    __shared__ float sS[BK * STR];   // S tile, transposed: sS[k*STR + r]
    __shared__ float sW[BK * 64];    // W tile: sW[k*64 + d]

    const int tid = threadIdx.x;
    const int n0  = blockIdx.x * BM;
    const float* Sb = g_wt + (size_t)n0 * KCDIM;

    const int tc4  = (tid & 15) * 4;   // output cols tc4..tc4+3
    const int tr8  = (tid >> 4) * 8;   // output rows tr8..tr8+7
    const int lrow = tid >> 3;         // S-tile load row (0..31), +32*i
    const int lk   = (tid & 7) * 4;    // S-tile load k offset
    const int wr   = tid >> 4;         // W-tile load rows wr, wr+16
    const int wc   = (tid & 15) * 4;

    unsigned long long acc[4][4];      // [row-pair][col]
    #pragma unroll
    for (int i = 0; i < 4; i++)
        #pragma unroll
        for (int j = 0; j < 4; j++) acc[i][j] = 0ull;

    for (int k0 = 0; k0 < KCDIM; k0 += BK) {
        float4 sv[4];
        #pragma unroll
        for (int i = 0; i < 4; i++)
            sv[i] = *(const float4*)(Sb + (size_t)(lrow + 32*i) * KCDIM + k0 + lk);
        const float4 wv0 = *(const float4*)(W + (size_t)(k0 + wr     ) * 64 + wc);
        const float4 wv1 = *(const float4*)(W + (size_t)(k0 + wr + 16) * 64 + wc);

        __syncthreads();   // previous iteration's compute done
        #pragma unroll
        for (int i = 0; i < 4; i++) {
            const int r = lrow + 32*i;
            sS[(lk+0)*STR + r] = sv[i].x;
            sS[(lk+1)*STR + r] = sv[i].y;
            sS[(lk+2)*STR + r] = sv[i].z;
            sS[(lk+3)*STR + r] = sv[i].w;
        }
        *(float4*)&sW[wr*64 + wc]      = wv0;
        *(float4*)&sW[(wr+16)*64 + wc] = wv1;
        __syncthreads();

        #pragma unroll
        for (int k = 0; k < BK; k++) {
            const float* sr = &sS[k*STR + tr8];
            const ulonglong2 p0 = *(const ulonglong2*)sr;        // row pairs 0,1
            const ulonglong2 p1 = *(const ulonglong2*)(sr + 4);  // row pairs 2,3
            const float4 b = *(const float4*)&sW[k*64 + tc4];
            const unsigned long long b0 = splat2(b.x);
            const unsigned long long b1 = splat2(b.y);
            const unsigned long long b2 = splat2(b.z);
            const unsigned long long b3 = splat2(b.w);
            acc[0][0] = ffma2(p0.x, b0, acc[0][0]);
            acc[0][1] = ffma2(p0.x, b1, acc[0][1]);
            acc[0][2] = ffma2(p0.x, b2, acc[0][2]);
            acc[0][3] = ffma2(p0.x, b3, acc[0][3]);
            acc[1][0] = ffma2(p0.y, b0, acc[1][0]);
            acc[1][1] = ffma2(p0.y, b1, acc[1][1]);
            acc[1][2] = ffma2(p0.y, b2, acc[1][2]);
            acc[1][3] = ffma2(p0.y, b3, acc[1][3]);
            acc[2][0] = ffma2(p1.x, b0, acc[2][0]);
            acc[2][1] = ffma2(p1.x, b1, acc[2][1]);
            acc[2][2] = ffma2(p1.x, b2, acc[2][2]);
            acc[2][3] = ffma2(p1.x, b3, acc[2][3]);
            acc[3][0] = ffma2(p1.y, b0, acc[3][0]);
            acc[3][1] = ffma2(p1.y, b1, acc[3][1]);
            acc[3][2] = ffma2(p1.y, b2, acc[3][2]);
            acc[3][3] = ffma2(p1.y, b3, acc[3][3]);
        }
    }

    #pragma unroll
    for (int rp = 0; rp < 4; rp++) {
        const float2 v0 = unpack2(acc[rp][0]);
        const float2 v1 = unpack2(acc[rp][1]);
        const float2 v2 = unpack2(acc[rp][2]);
        const float2 v3 = unpack2(acc[rp][3]);
        const int r = n0 + tr8 + 2*rp;
        if (r < NQ)
            *(float4*)&out[(size_t)r*64 + tc4] = make_float4(v0.x, v1.x, v2.x, v3.x);
        if (r + 1 < NQ)
            *(float4*)&out[(size_t)(r+1)*64 + tc4] = make_float4(v0.y, v1.y, v2.y, v3.y);
    }
}

// =============================================================================
extern "C" void kernel_launch(void* const* d_in, const int* in_sizes, int n_in,
                              void* d_out, int out_size) {
    const float* q_pts = (const float*)d_in[0];
    const float* s_pts = (const float*)d_in[1];
    const int*   nbi   = (const int*)  d_in[2];
    const float* x     = (const float*)d_in[3];
    const float* kp    = (const float*)d_in[4];
    const float* W     = (const float*)d_in[5];
    float* out = (float*)d_out;

    kpconv_stage1<<<NQ / 8, 256>>>(q_pts, s_pts, nbi, x, kp);
    kpconv_stage2<<<KPAD / BM, 256>>>(W, out);
}

// round 5
// speedup vs baseline: 1.4801x; 1.4801x over previous
#include <cuda_runtime.h>
#include <cuda_bf16.h>
#include <cstdint>

// ---------------- problem constants ----------------
#define NQ   50000
#define NMS  50000
#define NH   32
#define NK   15
#define NC   64
#define ND   64
#define KPAD 50048          // NQ padded to multiple of 128
#define KC2  1024           // 64 channels * 16 (k padded 15->16)

// scratch: hi/lo bf16 planes of weighted[n][c*16+k] (normalization folded in)
__device__ __nv_bfloat16 g_hi[(size_t)KPAD * KC2];   // ~102 MB
__device__ __nv_bfloat16 g_lo[(size_t)KPAD * KC2];   // ~102 MB
__device__ uint4         g_bfrag[64 * 8 * 32];       // B fragments, 256 KB
__device__ float         g_flag[NMS];                // rowsum>0 flags

// ---------------- helpers ----------------
__device__ __forceinline__ unsigned long long ffma2(unsigned long long a,
                                                    unsigned long long b,
                                                    unsigned long long c) {
    unsigned long long d;
    asm("fma.rn.f32x2 %0, %1, %2, %3;" : "=l"(d) : "l"(a), "l"(b), "l"(c));
    return d;
}
__device__ __forceinline__ unsigned long long splat2(float v) {
    unsigned long long d;
    asm("mov.b64 %0, {%1, %1};" : "=l"(d) : "f"(v));
    return d;
}
__device__ __forceinline__ float2 unpack2(unsigned long long v) {
    float2 r;
    asm("mov.b64 {%0, %1}, %2;" : "=f"(r.x), "=f"(r.y) : "l"(v));
    return r;
}
__device__ __forceinline__ unsigned long long mul2(unsigned long long a,
                                                   unsigned long long b) {
    unsigned long long d;
    asm("mul.rn.f32x2 %0, %1, %2;" : "=l"(d) : "l"(a), "l"(b));
    return d;
}
// pack bf16x2: low half = x (first elem in memory), high = y
__device__ __forceinline__ uint32_t pack_bf16x2(float x, float y) {
    uint32_t r;
    asm("cvt.rn.bf16x2.f32 %0, %1, %2;" : "=r"(r) : "f"(y), "f"(x));
    return r;
}
__device__ __forceinline__ uint32_t smem_u32(const void* p) {
    uint32_t a;
    asm("{ .reg .u64 t; cvta.to.shared.u64 t, %1; cvt.u32.u64 %0, t; }" : "=r"(a) : "l"(p));
    return a;
}
__device__ __forceinline__ void cp16(uint32_t dst, const void* src) {
    asm volatile("cp.async.cg.shared.global [%0], [%1], 16;" :: "r"(dst), "l"(src));
}
#define CP_COMMIT() asm volatile("cp.async.commit_group;" ::: "memory")
#define CP_WAIT0()  asm volatile("cp.async.wait_group 0;" ::: "memory")
#define CP_WAIT1()  asm volatile("cp.async.wait_group 1;" ::: "memory")
#define SWZ(o) ((o) ^ (((o) >> 3) & 0x70))

__device__ __forceinline__ void ldsm4(uint32_t& r0, uint32_t& r1, uint32_t& r2,
                                      uint32_t& r3, uint32_t addr) {
    asm volatile("ldmatrix.sync.aligned.m8n8.x4.shared.b16 {%0,%1,%2,%3}, [%4];"
        : "=r"(r0), "=r"(r1), "=r"(r2), "=r"(r3) : "r"(addr));
}
__device__ __forceinline__ void mma16816(float* d, const uint32_t* a,
                                         uint32_t b0, uint32_t b1) {
    asm volatile(
        "mma.sync.aligned.m16n8k16.row.col.f32.bf16.bf16.f32 "
        "{%0,%1,%2,%3}, {%4,%5,%6,%7}, {%8,%9}, {%0,%1,%2,%3};"
        : "+f"(d[0]), "+f"(d[1]), "+f"(d[2]), "+f"(d[3])
        : "r"(a[0]), "r"(a[1]), "r"(a[2]), "r"(a[3]), "r"(b0), "r"(b1));
}

// =============================================================================
// prep A: validity flags f[m] = (sum_c x[m,c] > 0)
// =============================================================================
__global__ void __launch_bounds__(256) prep_flags(const float* __restrict__ x) {
    const int w = threadIdx.x >> 5, l = threadIdx.x & 31;
    const int r = blockIdx.x * 16 + w * 2 + (l >> 4);
    const float4 v = ((const float4*)(x + (size_t)r * NC))[l & 15];
    float s = v.x + v.y + v.z + v.w;
    #pragma unroll
    for (int o = 1; o < 16; o <<= 1) s += __shfl_xor_sync(0xffffffffu, s, o);
    if ((l & 15) == 0) g_flag[r] = (s > 0.0f) ? 1.0f : 0.0f;
}

// =============================================================================
// prep B: pack W into m16n8k16 B-fragment order.
//   B[kc][n] = W[k_kp][c][n],  kc = c*16 + k_kp  (k_kp==15 -> 0 pad)
//   lane layout (col-major frag): n = ntile*8 + lane/4, k0 = 2*(lane&3)
//   g_bfrag[(kstep*8+ntile)*32+lane] = { hi(k0,k0+1), hi(k0+8,k0+9),
//                                        lo(k0,k0+1), lo(k0+8,k0+9) }
// =============================================================================
__device__ __forceinline__ float wval(const float* W, int kc, int n) {
    const int k_kp = kc & 15, c = kc >> 4;
    return (k_kp < NK) ? W[((size_t)k_kp * NC + c) * ND + n] : 0.0f;
}
__global__ void __launch_bounds__(256) prep_w(const float* __restrict__ W) {
    const int g     = blockIdx.x * 256 + threadIdx.x;   // 64*8*32 = 16384
    const int lane  = g & 31;
    const int ntile = (g >> 5) & 7;
    const int kstep = g >> 8;                           // 0..63
    const int n  = ntile * 8 + (lane >> 2);
    const int kc = kstep * 16 + 2 * (lane & 3);
    float v[4] = { wval(W, kc,     n), wval(W, kc + 1, n),
                   wval(W, kc + 8, n), wval(W, kc + 9, n) };
    float h[4], l[4];
    #pragma unroll
    for (int i = 0; i < 4; i++) {
        h[i] = __bfloat162float(__float2bfloat16(v[i]));
        l[i] = v[i] - h[i];
    }
    g_bfrag[g] = make_uint4(pack_bf16x2(h[0], h[1]), pack_bf16x2(h[2], h[3]),
                            pack_bf16x2(l[0], l[1]), pack_bf16x2(l[2], l[3]));
}

// =============================================================================
// Stage 1: weighted[n, c*16+k] = (1/nnum) sum_h w[n,h,k] * x[idx,c] -> bf16 hi/lo
// One warp per query; phase A lane=h, phase B lane=channel.
// =============================================================================
__global__ void __launch_bounds__(256) kpconv_stage1(
    const float* __restrict__ q_pts, const float* __restrict__ s_pts,
    const int*   __restrict__ nbi,   const float* __restrict__ x,
    const float* __restrict__ kp)
{
    __shared__ __align__(16) float ws[8][NH][16];
    __shared__ int idxs[8][NH];
    const int warp = threadIdx.x >> 5;
    const int lane = threadIdx.x & 31;
    const int n    = blockIdx.x * 8 + warp;

    // ---- phase A: lane = neighbor h ----
    const int idx = __ldg(&nbi[n * NH + lane]);
    const float qx = q_pts[n*3+0], qy = q_pts[n*3+1], qz = q_pts[n*3+2];
    const float dx = __ldg(&s_pts[idx*3+0]) - qx;
    const float dy = __ldg(&s_pts[idx*3+1]) - qy;
    const float dz = __ldg(&s_pts[idx*3+2]) - qz;
    const float vf = __ldg(&g_flag[idx]);
    #pragma unroll
    for (int k = 0; k < NK; k++) {
        const float ex = dx - kp[k*3+0];
        const float ey = dy - kp[k*3+1];
        const float ez = dz - kp[k*3+2];
        const float d2 = ex*ex + ey*ey + ez*ez;
        const float r  = __frsqrt_rn(fmaxf(d2, 1e-24f));
        ws[warp][lane][k] = fmaxf(1.0f - (d2 * r) * (1.0f / 1.2f), 0.0f);
    }
    ws[warp][lane][15] = 0.0f;
    idxs[warp][lane] = idx;
    const int cnt = __popc(__ballot_sync(0xffffffffu, vf > 0.0f));
    __syncwarp();

    // ---- phase B: lane = channel (c=lane, c=lane+32); acc packs k-pairs ----
    unsigned long long a0[8], a1[8];
    #pragma unroll
    for (int j = 0; j < 8; j++) { a0[j] = 0ull; a1[j] = 0ull; }

    #pragma unroll 8
    for (int h = 0; h < NH; h++) {
        const int ih = idxs[warp][h];
        const float* xr = x + (size_t)ih * NC;
        const unsigned long long xx0 = splat2(__ldg(&xr[lane]));
        const unsigned long long xx1 = splat2(__ldg(&xr[lane + 32]));
        const ulonglong2* wp = (const ulonglong2*)&ws[warp][h][0];
        #pragma unroll
        for (int j = 0; j < 4; j++) {
            const ulonglong2 w2 = wp[j];
            a0[2*j+0] = ffma2(w2.x, xx0, a0[2*j+0]);
            a0[2*j+1] = ffma2(w2.y, xx0, a0[2*j+1]);
            a1[2*j+0] = ffma2(w2.x, xx1, a1[2*j+0]);
            a1[2*j+1] = ffma2(w2.y, xx1, a1[2*j+1]);
        }
    }

    const float inv = 1.0f / (float)(cnt > 0 ? cnt : 1);
    const unsigned long long inv2 = splat2(inv);

    #pragma unroll
    for (int half = 0; half < 2; half++) {
        const int c = lane + half * 32;
        const unsigned long long* acc = half ? a1 : a0;
        uint32_t hi[8], lo[8];
        #pragma unroll
        for (int j = 0; j < 8; j++) {
            const float2 s = unpack2(mul2(acc[j], inv2));
            const uint32_t hp = pack_bf16x2(s.x, s.y);
            const __nv_bfloat162 hb = *(const __nv_bfloat162*)&hp;
            const float2 hf = __bfloat1622float2(hb);
            hi[j] = hp;
            lo[j] = pack_bf16x2(s.x - hf.x, s.y - hf.y);
        }
        const size_t base = (size_t)n * KC2 + c * 16;
        uint4* ph = (uint4*)(g_hi + base);
        uint4* pl = (uint4*)(g_lo + base);
        ph[0] = make_uint4(hi[0], hi[1], hi[2], hi[3]);
        ph[1] = make_uint4(hi[4], hi[5], hi[6], hi[7]);
        pl[0] = make_uint4(lo[0], lo[1], lo[2], lo[3]);
        pl[1] = make_uint4(lo[4], lo[5], lo[6], lo[7]);
    }
}

// =============================================================================
// Stage 2: out[KPAD,64] via mma.sync split-bf16 (AhBh + AhBl + AlBh).
// Block = 128 rows x 64 cols; 16 cp.async double-buffered chunks of kc=64.
// Warp w owns m-tile rows [w*16, w*16+16), all 8 n-tiles.
// Smem per buffer: A_hi 16K | A_lo 16K | Bfrag 16K  (2 buffers = 96 KB)
// =============================================================================
#define S2_THREADS 256
#define BUFB 49152
#define OFF_ALO 16384
#define OFF_BF  32768
#define SM_TOT  (2 * BUFB)

__device__ __forceinline__ void s2_issue(uint32_t sb, int buf, int chunk, int tid,
                                         const char* Ahi, const char* Alo) {
    const uint32_t base = sb + buf * BUFB;
    #pragma unroll
    for (int i = 0; i < 8; i++) {                 // A: 2 planes x 128 rows x 128B
        const int ch   = i * S2_THREADS + tid;    // 0..2047
        const int rr   = (ch >> 3) & 127;
        const int c16  = (ch & 7) * 16;
        const uint32_t d = SWZ((uint32_t)(rr * 128 + c16));
        const size_t  src = (size_t)rr * 2048 + chunk * 128 + c16;
        if (i < 4) cp16(base + d, Ahi + src);
        else       cp16(base + OFF_ALO + d, Alo + src);
    }
    #pragma unroll
    for (int i = 0; i < 4; i++) {                 // B frags: 16 KB linear
        const int ch = i * S2_THREADS + tid;      // 0..1023
        cp16(base + OFF_BF + ch * 16, (const char*)g_bfrag + ((size_t)chunk * 1024 + ch) * 16);
    }
}

__global__ void __launch_bounds__(S2_THREADS) kpconv_stage2(float* __restrict__ out) {
    extern __shared__ __align__(1024) char smem[];
    const uint32_t sb = smem_u32(smem);
    const int tid  = threadIdx.x;
    const int wid  = tid >> 5;
    const int lane = tid & 31;
    const int n0   = blockIdx.x * 128;
    const int m0   = wid * 16;

    const char* Ahi = (const char*)(g_hi + (size_t)n0 * KC2);
    const char* Alo = (const char*)(g_lo + (size_t)n0 * KC2);

    float d[8][4];
    #pragma unroll
    for (int t = 0; t < 8; t++)
        #pragma unroll
        for (int j = 0; j < 4; j++) d[t][j] = 0.0f;

    // A ldmatrix lane address pattern: row = m0+(lane&15), col-half = lane>>4
    const uint32_t arow = (uint32_t)(m0 + (lane & 15));
    const uint32_t ahalf = (uint32_t)((lane >> 4) * 16);   // bytes

    s2_issue(sb, 0, 0, tid, Ahi, Alo);
    CP_COMMIT();

    for (int ch = 0; ch < 16; ch++) {
        if (ch + 1 < 16) {
            s2_issue(sb, (ch + 1) & 1, ch + 1, tid, Ahi, Alo);
            CP_COMMIT();
            CP_WAIT1();
        } else {
            CP_WAIT0();
        }
        __syncthreads();

        const uint32_t base = sb + (ch & 1) * BUFB;
        #pragma unroll
        for (int ks = 0; ks < 4; ks++) {
            const uint32_t aoff = SWZ(arow * 128 + (uint32_t)(ks * 32) + ahalf);
            uint32_t ah[4], al[4];
            ldsm4(ah[0], ah[1], ah[2], ah[3], base + aoff);
            ldsm4(al[0], al[1], al[2], al[3], base + OFF_ALO + aoff);
            const uint32_t bbase = base + OFF_BF + (uint32_t)(ks * 8 * 32 + lane) * 16;
            #pragma unroll
            for (int nt = 0; nt < 8; nt++) {
                const uint4 b = *(const uint4*)(size_t)0; // placeholder (never used)
                (void)b;
                uint4 bf;
                asm volatile("ld.shared.v4.b32 {%0,%1,%2,%3}, [%4];"
                    : "=r"(bf.x), "=r"(bf.y), "=r"(bf.z), "=r"(bf.w)
                    : "r"(bbase + (uint32_t)(nt * 32 * 16)));
                mma16816(d[nt], ah, bf.x, bf.y);   // Ahi * Bhi
                mma16816(d[nt], ah, bf.z, bf.w);   // Ahi * Blo
                mma16816(d[nt], al, bf.x, bf.y);   // Alo * Bhi
            }
        }
        __syncthreads();
    }

    // epilogue: frag C layout -> rows r0=t/4, r1=t/4+8; cols 2*(t%4)+{0,1}
    const int r0 = n0 + m0 + (lane >> 2);
    const int r1 = r0 + 8;
    const int c0 = (lane & 3) * 2;
    #pragma unroll
    for (int nt = 0; nt < 8; nt++) {
        const int c = nt * 8 + c0;
        if (r0 < NQ) *(float2*)(out + (size_t)r0 * ND + c) = make_float2(d[nt][0], d[nt][1]);
        if (r1 < NQ) *(float2*)(out + (size_t)r1 * ND + c) = make_float2(d[nt][2], d[nt][3]);
    }
}

// =============================================================================
extern "C" void kernel_launch(void* const* d_in, const int* in_sizes, int n_in,
                              void* d_out, int out_size) {
    const float* q_pts = (const float*)d_in[0];
    const float* s_pts = (const float*)d_in[1];
    const int*   nbi   = (const int*)  d_in[2];
    const float* x     = (const float*)d_in[3];
    const float* kp    = (const float*)d_in[4];
    const float* W     = (const float*)d_in[5];
    float* out = (float*)d_out;

    cudaFuncSetAttribute(kpconv_stage2, cudaFuncAttributeMaxDynamicSharedMemorySize, SM_TOT);

    prep_flags<<<NMS / 16, 256>>>(x);
    prep_w<<<64, 256>>>(W);
    kpconv_stage1<<<NQ / 8, 256>>>(q_pts, s_pts, nbi, x, kp);
    kpconv_stage2<<<KPAD / 128, S2_THREADS, SM_TOT>>>(out);
}